// round 15
// baseline (speedup 1.0000x reference)
#include <cuda_runtime.h>
#include <stdint.h>

// Problem constants
#define Bdim 2
#define Sdim 4096
#define Ddim 768
#define Hnum 12
#define DKdim 64
#define BHnum (Bdim * Hnum)        // 24
#define MROWS (Bdim * Sdim)        // 8192
#define QSCALE (0.125f * 1.4426950408889634f)   // 1/sqrt(64) * log2(e)

// Scratch (device globals). All interchange data is fp16x2-packed (uint32).
__device__ uint32_t g_qr[(size_t)MROWS * Ddim / 2];
__device__ uint32_t g_kr[(size_t)MROWS * Ddim / 2];
__device__ uint32_t g_vr[(size_t)MROWS * Ddim / 2];
__device__ uint32_t g_wq[(size_t)Ddim * Ddim / 2];
__device__ uint32_t g_wk[(size_t)Ddim * Ddim / 2];
__device__ uint32_t g_wv[(size_t)Ddim * Ddim / 2];
__device__ uint32_t g_wo[(size_t)Ddim * Ddim / 2];
__device__ uint32_t g_Qh[(size_t)BHnum * Sdim * 32];   // [bh][s][dk/2], prescaled
__device__ uint32_t g_Kh[(size_t)BHnum * Sdim * 32];
__device__ uint32_t g_Vh[(size_t)BHnum * Sdim * 32];
__device__ uint32_t g_ctx[(size_t)MROWS * Ddim / 2];

// ---------------------------------------------------------------------------
// PTX helpers
// ---------------------------------------------------------------------------
__device__ __forceinline__ void mma_f16(float* c, const uint32_t* a, uint32_t b0, uint32_t b1) {
    asm("mma.sync.aligned.m16n8k16.row.col.f32.f16.f16.f32 "
        "{%0,%1,%2,%3},{%4,%5,%6,%7},{%8,%9},{%0,%1,%2,%3};"
        : "+f"(c[0]), "+f"(c[1]), "+f"(c[2]), "+f"(c[3])
        : "r"(a[0]), "r"(a[1]), "r"(a[2]), "r"(a[3]), "r"(b0), "r"(b1));
}
__device__ __forceinline__ uint32_t pkh2(float lo, float hi) {
    uint32_t r;
    asm("cvt.rn.f16x2.f32 %0, %1, %2;" : "=r"(r) : "f"(hi), "f"(lo));
    return r;
}
__device__ __forceinline__ float ex2(float x) {
    float r;
    asm("ex2.approx.ftz.f32 %0, %1;" : "=f"(r) : "f"(x));
    return r;
}
__device__ __forceinline__ uint32_t sptr(const void* p) {
    return (uint32_t)__cvta_generic_to_shared(p);
}
__device__ __forceinline__ void ldmx4(uint32_t* r, uint32_t addr) {
    asm volatile("ldmatrix.sync.aligned.m8n8.x4.shared.b16 {%0,%1,%2,%3}, [%4];"
                 : "=r"(r[0]), "=r"(r[1]), "=r"(r[2]), "=r"(r[3]) : "r"(addr));
}
__device__ __forceinline__ void ldmx4t(uint32_t& r0, uint32_t& r1, uint32_t& r2, uint32_t& r3,
                                       uint32_t addr) {
    asm volatile("ldmatrix.sync.aligned.m8n8.x4.trans.shared.b16 {%0,%1,%2,%3}, [%4];"
                 : "=r"(r0), "=r"(r1), "=r"(r2), "=r"(r3) : "r"(addr));
}
__device__ __forceinline__ void cpa16(uint32_t dst, const void* src) {
    asm volatile("cp.async.ca.shared.global [%0], [%1], 16;" :: "r"(dst), "l"(src));
}
#define CP_COMMIT() asm volatile("cp.async.commit_group;")
#define CP_WAIT0()  asm volatile("cp.async.wait_group 0;")

// ---------------------------------------------------------------------------
// Pre-round pass (merged): f32 -> fp16. y<3: q/k/v inputs; y>=3: weights
// (Wq pre-scaled by QSCALE). Oversized grid slices early-exit.
// ---------------------------------------------------------------------------
#define IN_BLOCKS ((MROWS * Ddim) / 2048)   // 3072
#define W_BLOCKS  ((Ddim * Ddim) / 2048)    // 288

__global__ __launch_bounds__(256) void preround_all(const float* __restrict__ q,
                                                    const float* __restrict__ k,
                                                    const float* __restrict__ v,
                                                    const float* __restrict__ Wq,
                                                    const float* __restrict__ Wk,
                                                    const float* __restrict__ Wv,
                                                    const float* __restrict__ Wo)
{
    const int y = blockIdx.y;
    if (y >= 3 && blockIdx.x >= W_BLOCKS) return;
    const size_t i = ((size_t)blockIdx.x * 256 + threadIdx.x) * 8;
    const float* s;
    uint32_t* d;
    float sc = 1.0f;
    switch (y) {
        case 0: s = q;  d = g_qr; break;
        case 1: s = k;  d = g_kr; break;
        case 2: s = v;  d = g_vr; break;
        case 3: s = Wq; d = g_wq; sc = QSCALE; break;
        case 4: s = Wk; d = g_wk; break;
        case 5: s = Wv; d = g_wv; break;
        default: s = Wo; d = g_wo; break;
    }
    float4 x0 = *(const float4*)(s + i);
    float4 x1 = *(const float4*)(s + i + 4);
    *(uint4*)(d + i / 2) = make_uint4(pkh2(x0.x * sc, x0.y * sc), pkh2(x0.z * sc, x0.w * sc),
                                      pkh2(x1.x * sc, x1.y * sc), pkh2(x1.z * sc, x1.w * sc));
}

// ---------------------------------------------------------------------------
// Projection GEMM (fp16 m16n8k16, cp.async 2-stage, BK=64, BM=64, BN=128):
// C = A @ W^T. 8 warps (2m x 4n), warp tile 32x32. 3 CTAs/SM.
// smem rows 72 halves (144B) -> conflict-free ldmatrix.
// ---------------------------------------------------------------------------
#define PSTW 36                      // row stride in words (72 halves = 144B)
#define ABUF (64 * PSTW)             // 2304 words (A tile: 64 rows)
#define BBUF (128 * PSTW)            // 4608 words (B tile: 128 rows)
#define STAGEW (ABUF + BBUF)         // 6912 words per stage
#define NKC (Ddim / 64)              // 12 chunks
#define PROJ_SMEM (2 * STAGEW * 4)   // 55296 B

__device__ __forceinline__ void proj_stage(const uint32_t* __restrict__ Ap,
                                           const uint32_t* __restrict__ W,
                                           uint32_t* base, int kc, int m0, int n0)
{
    const int tid = threadIdx.x;
    if (tid < 128) {
        // A: 64 rows, 2 threads per row (each stages 16 words = 64B)
        const int r = tid >> 1;
        const int half = (tid & 1) * 16;
        const uint32_t* src = Ap + (size_t)(m0 + r) * (Ddim / 2) + kc * 32 + half;
        uint32_t dst = sptr(base + r * PSTW + half);
#pragma unroll
        for (int i = 0; i < 4; i++) cpa16(dst + i * 16, src + i * 4);
    } else {
        // B: 128 rows, 1 thread per row (32 words = 128B)
        const int r = tid - 128;
        const uint32_t* src = W + (size_t)(n0 + r) * (Ddim / 2) + kc * 32;
        uint32_t dst = sptr(base + ABUF + r * PSTW);
#pragma unroll
        for (int i = 0; i < 8; i++) cpa16(dst + i * 16, src + i * 4);
    }
}

__device__ __forceinline__ void proj_body(const uint32_t* __restrict__ Ap,
                                          const uint32_t* __restrict__ W,
                                          float* __restrict__ Cp, int mode,
                                          int m0, int n0, uint32_t* psm)
{
    const int tid = threadIdx.x;
    const int warp = tid >> 5;
    const int lane = tid & 31;
    const int g = lane >> 2;
    const int t = lane & 3;
    const int m0w = (warp >> 2) * 32;
    const int n0w = (warp & 3) * 32;
    const int lrow = lane & 15;
    const int lcol = (lane >> 4) * 16;

    float acc[2][4][4];
#pragma unroll
    for (int mf = 0; mf < 2; mf++)
#pragma unroll
        for (int nf = 0; nf < 4; nf++)
#pragma unroll
            for (int i = 0; i < 4; i++) acc[mf][nf][i] = 0.f;

    proj_stage(Ap, W, psm, 0, m0, n0);
    CP_COMMIT();
    CP_WAIT0();
    __syncthreads();

    for (int kc = 0; kc < NKC; kc++) {
        const int buf = kc & 1;
        if (kc + 1 < NKC) {
            proj_stage(Ap, W, psm + (buf ^ 1) * STAGEW, kc + 1, m0, n0);
            CP_COMMIT();
        }
        const uint32_t abase = sptr(psm + buf * STAGEW)
                             + (m0w + lrow) * 144 + lcol;
        const uint32_t bbase = sptr(psm + buf * STAGEW) + ABUF * 4
                             + (n0w + lrow) * 144 + lcol;
#pragma unroll
        for (int ks = 0; ks < 4; ks++) {
            uint32_t a[2][4];
#pragma unroll
            for (int mf = 0; mf < 2; mf++)
                ldmx4(a[mf], abase + mf * 2304 + ks * 32);
#pragma unroll
            for (int np2 = 0; np2 < 2; np2++) {
                uint32_t b[4];
                ldmx4(b, bbase + np2 * 2304 + ks * 32);
#pragma unroll
                for (int mf = 0; mf < 2; mf++) {
                    mma_f16(acc[mf][2 * np2],     a[mf], b[0], b[2]);
                    mma_f16(acc[mf][2 * np2 + 1], a[mf], b[1], b[3]);
                }
            }
        }
        if (kc + 1 < NKC) {
            CP_WAIT0();
            __syncthreads();
        }
    }

    // Epilogue
#pragma unroll
    for (int mf = 0; mf < 2; mf++) {
#pragma unroll
        for (int nf = 0; nf < 4; nf++) {
            int row = m0 + m0w + mf * 16 + g;
            int col = n0 + n0w + nf * 8 + 2 * t;
            if (mode == 3) {
                *(float2*)(Cp + (size_t)row * Ddim + col) =
                    make_float2(acc[mf][nf][0], acc[mf][nf][1]);
                *(float2*)(Cp + (size_t)(row + 8) * Ddim + col) =
                    make_float2(acc[mf][nf][2], acc[mf][nf][3]);
            } else {
                int h = col >> 6, dk = col & 63;
                int b = row >> 12;
                int s = row & 4095;
                size_t r0 = (size_t)(b * Hnum + h) * Sdim + s;
                size_t r1 = r0 + 8;
                uint32_t* base = (mode == 0) ? g_Qh : (mode == 1) ? g_Kh : g_Vh;
                base[r0 * 32 + (dk >> 1)] = pkh2(acc[mf][nf][0], acc[mf][nf][1]);
                base[r1 * 32 + (dk >> 1)] = pkh2(acc[mf][nf][2], acc[mf][nf][3]);
            }
        }
    }
}

__global__ __launch_bounds__(256, 3) void proj_qkv()
{
    extern __shared__ uint32_t psm[];
    const int z = blockIdx.z;
    const uint32_t* A = (z == 0) ? g_qr : (z == 1) ? g_kr : g_vr;
    const uint32_t* W = (z == 0) ? g_wq : (z == 1) ? g_wk : g_wv;
    proj_body(A, W, nullptr, z, blockIdx.y * 64, blockIdx.x * 128, psm);
}

__global__ __launch_bounds__(256, 3) void proj_out(float* __restrict__ Cp)
{
    extern __shared__ uint32_t psm[];
    proj_body(g_ctx, g_wo, Cp, 3, blockIdx.y * 64, blockIdx.x * 128, psm);
}

// ---------------------------------------------------------------------------
// Flash attention (R8 version, verbatim): all-fp16 operands. BQ=128, BK=64.
// QK^T and PV both fp16 m16n8k16; frags via ldmatrix; K/V cp.async
// double-buffered; softmax in exp2 domain. smem rows: 72 halves (144B).
// ---------------------------------------------------------------------------
#define FSTW 36
#define QS_W (128 * FSTW)
#define KS_W (64 * FSTW)
#define VS_W (64 * FSTW)
#define FLASH_SMEM ((QS_W + 2 * KS_W + 2 * VS_W) * 4)   // 55296 B

__global__ __launch_bounds__(256, 2) void flash_tc()
{
    extern __shared__ uint32_t fsm[];
    uint32_t* Qs = fsm;                   // [128][72h] fp16 (prescaled)
    uint32_t* Ks = fsm + QS_W;            // 2 x [64][72h]
    uint32_t* Vs = fsm + QS_W + 2 * KS_W; // 2 x [64][72h], layout [j][dk]

    const int qb = (gridDim.x - 1) - blockIdx.x;
    const int bh = blockIdx.y;
    const uint32_t* Qg = g_Qh + (size_t)bh * Sdim * 32;
    const uint32_t* Kg = g_Kh + (size_t)bh * Sdim * 32;
    const uint32_t* Vg = g_Vh + (size_t)bh * Sdim * 32;

    const int tid = threadIdx.x;
    const int warp = tid >> 5;
    const int lane = tid & 31;
    const int g = lane >> 2;
    const int t = lane & 3;
    const int r0w = warp * 16;
    const int lrow = lane & 15;
    const int lcol = (lane >> 4) * 16;

    const int srow = tid >> 2;            // staging row 0..63
    const int sc8  = (tid & 3) * 8;       // staging word offset

    // Stage Q (all 128 rows) + K/V tile 0 into buffer 0
    {
        const int row = tid >> 1;
        const int cw = (tid & 1) * 16;
        uint32_t dq = sptr(&Qs[row * FSTW + cw]);
        const uint32_t* sq = Qg + (size_t)(qb * 128 + row) * 32 + cw;
#pragma unroll
        for (int i = 0; i < 4; i++) cpa16(dq + i * 16, sq + i * 4);

        uint32_t dk = sptr(&Ks[srow * FSTW + sc8]);
        const uint32_t* sk = Kg + (size_t)srow * 32 + sc8;
        cpa16(dk, sk); cpa16(dk + 16, sk + 4);

        uint32_t dv = sptr(&Vs[srow * FSTW + sc8]);
        const uint32_t* sv = Vg + (size_t)srow * 32 + sc8;
        cpa16(dv, sv); cpa16(dv + 16, sv + 4);
    }
    CP_COMMIT();
    CP_WAIT0();
    __syncthreads();

    float m_[2] = {-1e30f, -1e30f};
    float l_[2] = {0.f, 0.f};
    float o[8][4];
#pragma unroll
    for (int nf = 0; nf < 8; nf++)
#pragma unroll
        for (int i = 0; i < 4; i++) o[nf][i] = 0.f;

    const uint32_t qbase = sptr(Qs);
    const int jmax = 2 * qb + 1;
    for (int j = 0; j <= jmax; j++) {
        const int buf = j & 1;
        const uint32_t kbase = sptr(Ks + buf * KS_W);
        const uint32_t vbase = sptr(Vs + buf * VS_W);

        // Prefetch tile j+1 into the other buffer
        if (j < jmax) {
            const int bn = buf ^ 1;
            uint32_t dk = sptr(&Ks[bn * KS_W + srow * FSTW + sc8]);
            const uint32_t* sk = Kg + (size_t)((j + 1) * 64 + srow) * 32 + sc8;
            cpa16(dk, sk); cpa16(dk + 16, sk + 4);
            uint32_t dv = sptr(&Vs[bn * VS_W + srow * FSTW + sc8]);
            const uint32_t* sv = Vg + (size_t)((j + 1) * 64 + srow) * 32 + sc8;
            cpa16(dv, sv); cpa16(dv + 16, sv + 4);
            CP_COMMIT();
        }

        // ---- S = Q @ K^T (fp16 m16n8k16) ----
        float sacc[8][4];
#pragma unroll
        for (int nf = 0; nf < 8; nf++)
#pragma unroll
            for (int i = 0; i < 4; i++) sacc[nf][i] = 0.f;

#pragma unroll
        for (int ks = 0; ks < 4; ks++) {
            uint32_t a[4];
            ldmx4(a, qbase + (r0w + lrow) * 144 + ks * 32 + lcol);
#pragma unroll
            for (int np2 = 0; np2 < 4; np2++) {
                uint32_t b[4];
                ldmx4(b, kbase + (np2 * 16 + lrow) * 144 + ks * 32 + lcol);
                mma_f16(sacc[2 * np2],     a, b[0], b[2]);
                mma_f16(sacc[2 * np2 + 1], a, b[1], b[3]);
            }
        }

        // ---- causal mask on diagonal tiles ----
        if (j >= 2 * qb) {
            const int rg0 = qb * 128 + r0w + g;
            const int rg1 = rg0 + 8;
            const int cb = j * 64;
#pragma unroll
            for (int nf = 0; nf < 8; nf++) {
#pragma unroll
                for (int c = 0; c < 2; c++) {
                    int col = cb + nf * 8 + 2 * t + c;
                    if (col > rg0) sacc[nf][c] = -1e30f;
                    if (col > rg1) sacc[nf][2 + c] = -1e30f;
                }
            }
        }

        // ---- online softmax (exp2 domain) ----
#pragma unroll
        for (int r = 0; r < 2; r++) {
            const int off = r * 2;
            float tm = -1e30f;
#pragma unroll
            for (int nf = 0; nf < 8; nf++)
                tm = fmaxf(tm, fmaxf(sacc[nf][off], sacc[nf][off + 1]));
            tm = fmaxf(tm, __shfl_xor_sync(0xffffffffu, tm, 1));
            tm = fmaxf(tm, __shfl_xor_sync(0xffffffffu, tm, 2));
            float mnew = fmaxf(m_[r], tm);
            float fac = ex2(m_[r] - mnew);
            float rs = 0.f;
#pragma unroll
            for (int nf = 0; nf < 8; nf++) {
                float p0 = ex2(sacc[nf][off] - mnew);
                float p1 = ex2(sacc[nf][off + 1] - mnew);
                sacc[nf][off] = p0;
                sacc[nf][off + 1] = p1;
                rs += p0 + p1;
            }
            rs += __shfl_xor_sync(0xffffffffu, rs, 1);
            rs += __shfl_xor_sync(0xffffffffu, rs, 2);
            l_[r] = l_[r] * fac + rs;
            m_[r] = mnew;
#pragma unroll
            for (int nf = 0; nf < 8; nf++) {
                o[nf][off] *= fac;
                o[nf][off + 1] *= fac;
            }
        }

        // ---- pack P to fp16 A-frags (registers only) ----
        uint32_t ap[4][4];
#pragma unroll
        for (int kb = 0; kb < 4; kb++) {
            ap[kb][0] = pkh2(sacc[2 * kb][0], sacc[2 * kb][1]);
            ap[kb][1] = pkh2(sacc[2 * kb][2], sacc[2 * kb][3]);
            ap[kb][2] = pkh2(sacc[2 * kb + 1][0], sacc[2 * kb + 1][1]);
            ap[kb][3] = pkh2(sacc[2 * kb + 1][2], sacc[2 * kb + 1][3]);
        }

        // ---- O += P @ V (fp16, V B-frags via ldmatrix.trans) ----
#pragma unroll
        for (int np = 0; np < 4; np++) {
#pragma unroll
            for (int kb = 0; kb < 4; kb++) {
                uint32_t haddr = (uint32_t)((kb * 16 + lrow) * (2 * FSTW)
                                            + np * 16 + ((lane & 16) >> 1));
                uint32_t r0, r1, r2, r3;
                ldmx4t(r0, r1, r2, r3, vbase + haddr * 2);
                mma_f16(o[2 * np],     ap[kb], r0, r1);
                mma_f16(o[2 * np + 1], ap[kb], r2, r3);
            }
        }

        if (j < jmax) CP_WAIT0();
        __syncthreads();
    }

    // ---- epilogue: normalize, pack fp16 ctx ----
    const int b = bh / Hnum;
    const int h = bh % Hnum;
    const float inv0 = 1.f / l_[0];
    const float inv1 = 1.f / l_[1];
    const int row0 = qb * 128 + r0w + g;
#pragma unroll
    for (int nf = 0; nf < 8; nf++) {
        int cw = h * 32 + nf * 4 + t;
        g_ctx[(size_t)(b * Sdim + row0) * (Ddim / 2) + cw] =
            pkh2(o[nf][0] * inv0, o[nf][1] * inv0);
        g_ctx[(size_t)(b * Sdim + row0 + 8) * (Ddim / 2) + cw] =
            pkh2(o[nf][2] * inv1, o[nf][3] * inv1);
    }
}

// ---------------------------------------------------------------------------
// Launch
// ---------------------------------------------------------------------------
extern "C" void kernel_launch(void* const* d_in, const int* in_sizes, int n_in,
                              void* d_out, int out_size)
{
    const float* q  = (const float*)d_in[0];
    const float* k  = (const float*)d_in[1];
    const float* v  = (const float*)d_in[2];
    const float* Wq = (const float*)d_in[3];
    const float* Wk = (const float*)d_in[4];
    const float* Wv = (const float*)d_in[5];
    const float* Wo = (const float*)d_in[6];
    // d_in[7] = mask: known causal tril, handled analytically in flash_tc
    float* out = (float*)d_out;

    cudaFuncSetAttribute(proj_qkv, cudaFuncAttributeMaxDynamicSharedMemorySize, PROJ_SMEM);
    cudaFuncSetAttribute(proj_out, cudaFuncAttributeMaxDynamicSharedMemorySize, PROJ_SMEM);
    cudaFuncSetAttribute(flash_tc, cudaFuncAttributeMaxDynamicSharedMemorySize, FLASH_SMEM);

    preround_all<<<dim3(IN_BLOCKS, 7), 256>>>(q, k, v, Wq, Wk, Wv, Wo);

    proj_qkv<<<dim3(Ddim / 128, MROWS / 64, 3), 256, PROJ_SMEM>>>();

    flash_tc<<<dim3(Sdim / 128, BHnum), 256, FLASH_SMEM>>>();

    proj_out<<<dim3(Ddim / 128, MROWS / 64), 256, PROJ_SMEM>>>(out);
}

// round 16
// speedup vs baseline: 1.1311x; 1.1311x over previous
#include <cuda_runtime.h>
#include <stdint.h>

// Problem constants
#define Bdim 2
#define Sdim 4096
#define Ddim 768
#define Hnum 12
#define DKdim 64
#define BHnum (Bdim * Hnum)        // 24
#define MROWS (Bdim * Sdim)        // 8192
#define QSCALE (0.125f * 1.4426950408889634f)   // 1/sqrt(64) * log2(e)

// Scratch (device globals). All interchange data is fp16x2-packed (uint32).
__device__ uint32_t g_qr[(size_t)MROWS * Ddim / 2];
__device__ uint32_t g_kr[(size_t)MROWS * Ddim / 2];
__device__ uint32_t g_vr[(size_t)MROWS * Ddim / 2];
__device__ uint32_t g_wq[(size_t)Ddim * Ddim / 2];
__device__ uint32_t g_wk[(size_t)Ddim * Ddim / 2];
__device__ uint32_t g_wv[(size_t)Ddim * Ddim / 2];
__device__ uint32_t g_wo[(size_t)Ddim * Ddim / 2];
__device__ uint32_t g_Qh[(size_t)BHnum * Sdim * 32];   // [bh][s][dk/2], prescaled
__device__ uint32_t g_Kh[(size_t)BHnum * Sdim * 32];
__device__ uint32_t g_Vh[(size_t)BHnum * Sdim * 32];
__device__ uint32_t g_ctx[(size_t)MROWS * Ddim / 2];

// ---------------------------------------------------------------------------
// PTX helpers
// ---------------------------------------------------------------------------
__device__ __forceinline__ void mma_f16(float* c, const uint32_t* a, uint32_t b0, uint32_t b1) {
    asm("mma.sync.aligned.m16n8k16.row.col.f32.f16.f16.f32 "
        "{%0,%1,%2,%3},{%4,%5,%6,%7},{%8,%9},{%0,%1,%2,%3};"
        : "+f"(c[0]), "+f"(c[1]), "+f"(c[2]), "+f"(c[3])
        : "r"(a[0]), "r"(a[1]), "r"(a[2]), "r"(a[3]), "r"(b0), "r"(b1));
}
__device__ __forceinline__ uint32_t pkh2(float lo, float hi) {
    uint32_t r;
    asm("cvt.rn.f16x2.f32 %0, %1, %2;" : "=r"(r) : "f"(hi), "f"(lo));
    return r;
}
__device__ __forceinline__ float ex2(float x) {
    float r;
    asm("ex2.approx.ftz.f32 %0, %1;" : "=f"(r) : "f"(x));
    return r;
}
__device__ __forceinline__ uint32_t sptr(const void* p) {
    return (uint32_t)__cvta_generic_to_shared(p);
}
__device__ __forceinline__ void ldmx4(uint32_t* r, uint32_t addr) {
    asm volatile("ldmatrix.sync.aligned.m8n8.x4.shared.b16 {%0,%1,%2,%3}, [%4];"
                 : "=r"(r[0]), "=r"(r[1]), "=r"(r[2]), "=r"(r[3]) : "r"(addr));
}
__device__ __forceinline__ void ldmx4t(uint32_t& r0, uint32_t& r1, uint32_t& r2, uint32_t& r3,
                                       uint32_t addr) {
    asm volatile("ldmatrix.sync.aligned.m8n8.x4.trans.shared.b16 {%0,%1,%2,%3}, [%4];"
                 : "=r"(r0), "=r"(r1), "=r"(r2), "=r"(r3) : "r"(addr));
}
__device__ __forceinline__ void cpa16(uint32_t dst, const void* src) {
    asm volatile("cp.async.ca.shared.global [%0], [%1], 16;" :: "r"(dst), "l"(src));
}
#define CP_COMMIT() asm volatile("cp.async.commit_group;")
#define CP_WAIT0()  asm volatile("cp.async.wait_group 0;")

// ---------------------------------------------------------------------------
// Pre-round pass (merged, single launch): f32 -> fp16. y<3: q/k/v inputs;
// y>=3: weights (Wq pre-scaled by QSCALE). Short slices early-exit.
// ---------------------------------------------------------------------------
#define IN_BLOCKS ((MROWS * Ddim) / 2048)   // 3072
#define W_BLOCKS  ((Ddim * Ddim) / 2048)    // 288

__global__ __launch_bounds__(256) void preround_all(const float* __restrict__ q,
                                                    const float* __restrict__ k,
                                                    const float* __restrict__ v,
                                                    const float* __restrict__ Wq,
                                                    const float* __restrict__ Wk,
                                                    const float* __restrict__ Wv,
                                                    const float* __restrict__ Wo)
{
    const int y = blockIdx.y;
    if (y >= 3 && blockIdx.x >= W_BLOCKS) return;
    const size_t i = ((size_t)blockIdx.x * 256 + threadIdx.x) * 8;
    const float* s;
    uint32_t* d;
    float sc = 1.0f;
    switch (y) {
        case 0: s = q;  d = g_qr; break;
        case 1: s = k;  d = g_kr; break;
        case 2: s = v;  d = g_vr; break;
        case 3: s = Wq; d = g_wq; sc = QSCALE; break;
        case 4: s = Wk; d = g_wk; break;
        case 5: s = Wv; d = g_wv; break;
        default: s = Wo; d = g_wo; break;
    }
    float4 x0 = *(const float4*)(s + i);
    float4 x1 = *(const float4*)(s + i + 4);
    *(uint4*)(d + i / 2) = make_uint4(pkh2(x0.x * sc, x0.y * sc), pkh2(x0.z * sc, x0.w * sc),
                                      pkh2(x1.x * sc, x1.y * sc), pkh2(x1.z * sc, x1.w * sc));
}

// ---------------------------------------------------------------------------
// Projection GEMM (R12 configuration: fp16 m16n8k16, cp.async 2-stage,
// BM=BN=128, BK=64): C = A @ W^T. 8 warps (2m x 4n), warp tile 64x32.
// smem rows 72 halves (144B) -> conflict-free ldmatrix.
// ---------------------------------------------------------------------------
#define PSTW 36                      // row stride in words (72 halves = 144B)
#define PBUF (128 * PSTW)            // 4608 words per operand tile (18KB)
#define NKC (Ddim / 64)              // 12 chunks
#define PROJ_SMEM (4 * PBUF * 4)     // 73728 B

__device__ __forceinline__ void proj_stage(const uint32_t* __restrict__ Ap,
                                           const uint32_t* __restrict__ W,
                                           uint32_t* base, int kc, int m0, int n0)
{
    const int tid = threadIdx.x;
    const int r = tid & 127;
    // one 128B row (64 halves) per thread: threads <128 stage A, >=128 stage B
    const uint32_t* src = (tid < 128)
        ? Ap + (size_t)(m0 + r) * (Ddim / 2) + kc * 32
        : W  + (size_t)(n0 + r) * (Ddim / 2) + kc * 32;
    uint32_t dst = sptr(base + ((tid < 128) ? 0 : PBUF) + r * PSTW);
#pragma unroll
    for (int i = 0; i < 8; i++) cpa16(dst + i * 16, src + i * 4);
}

__device__ __forceinline__ void proj_body(const uint32_t* __restrict__ Ap,
                                          const uint32_t* __restrict__ W,
                                          float* __restrict__ Cp, int mode,
                                          int m0, int n0, uint32_t* psm)
{
    const int tid = threadIdx.x;
    const int warp = tid >> 5;
    const int lane = tid & 31;
    const int g = lane >> 2;
    const int t = lane & 3;
    const int m0w = (warp >> 2) * 64;
    const int n0w = (warp & 3) * 32;
    const int lrow = lane & 15;
    const int lcol = (lane >> 4) * 16;

    float acc[4][4][4];
#pragma unroll
    for (int mf = 0; mf < 4; mf++)
#pragma unroll
        for (int nf = 0; nf < 4; nf++)
#pragma unroll
            for (int i = 0; i < 4; i++) acc[mf][nf][i] = 0.f;

    proj_stage(Ap, W, psm, 0, m0, n0);
    CP_COMMIT();
    CP_WAIT0();
    __syncthreads();

    for (int kc = 0; kc < NKC; kc++) {
        const int buf = kc & 1;
        if (kc + 1 < NKC) {
            proj_stage(Ap, W, psm + (buf ^ 1) * 2 * PBUF, kc + 1, m0, n0);
            CP_COMMIT();
        }
        const uint32_t abase = sptr(psm + buf * 2 * PBUF)
                             + (m0w + lrow) * 144 + lcol;
        const uint32_t bbase = sptr(psm + buf * 2 * PBUF) + PBUF * 4
                             + (n0w + lrow) * 144 + lcol;
#pragma unroll
        for (int ks = 0; ks < 4; ks++) {
            uint32_t a[4][4];
#pragma unroll
            for (int mf = 0; mf < 4; mf++)
                ldmx4(a[mf], abase + mf * 2304 + ks * 32);
#pragma unroll
            for (int np2 = 0; np2 < 2; np2++) {
                uint32_t b[4];
                ldmx4(b, bbase + np2 * 2304 + ks * 32);
#pragma unroll
                for (int mf = 0; mf < 4; mf++) {
                    mma_f16(acc[mf][2 * np2],     a[mf], b[0], b[2]);
                    mma_f16(acc[mf][2 * np2 + 1], a[mf], b[1], b[3]);
                }
            }
        }
        if (kc + 1 < NKC) {
            CP_WAIT0();
            __syncthreads();
        }
    }

    // Epilogue
#pragma unroll
    for (int mf = 0; mf < 4; mf++) {
#pragma unroll
        for (int nf = 0; nf < 4; nf++) {
            int row = m0 + m0w + mf * 16 + g;
            int col = n0 + n0w + nf * 8 + 2 * t;
            if (mode == 3) {
                *(float2*)(Cp + (size_t)row * Ddim + col) =
                    make_float2(acc[mf][nf][0], acc[mf][nf][1]);
                *(float2*)(Cp + (size_t)(row + 8) * Ddim + col) =
                    make_float2(acc[mf][nf][2], acc[mf][nf][3]);
            } else {
                int h = col >> 6, dk = col & 63;
                int b = row >> 12;
                int s = row & 4095;
                size_t r0 = (size_t)(b * Hnum + h) * Sdim + s;
                size_t r1 = r0 + 8;
                uint32_t* base = (mode == 0) ? g_Qh : (mode == 1) ? g_Kh : g_Vh;
                base[r0 * 32 + (dk >> 1)] = pkh2(acc[mf][nf][0], acc[mf][nf][1]);
                base[r1 * 32 + (dk >> 1)] = pkh2(acc[mf][nf][2], acc[mf][nf][3]);
            }
        }
    }
}

__global__ __launch_bounds__(256, 2) void proj_qkv()
{
    extern __shared__ uint32_t psm[];
    const int z = blockIdx.z;
    const uint32_t* A = (z == 0) ? g_qr : (z == 1) ? g_kr : g_vr;
    const uint32_t* W = (z == 0) ? g_wq : (z == 1) ? g_wk : g_wv;
    proj_body(A, W, nullptr, z, blockIdx.y * 128, blockIdx.x * 128, psm);
}

__global__ __launch_bounds__(256, 2) void proj_out(float* __restrict__ Cp)
{
    extern __shared__ uint32_t psm[];
    proj_body(g_ctx, g_wo, Cp, 3, blockIdx.y * 128, blockIdx.x * 128, psm);
}

// ---------------------------------------------------------------------------
// Flash attention (R8 version, verbatim): all-fp16 operands. BQ=128, BK=64.
// QK^T and PV both fp16 m16n8k16; frags via ldmatrix; K/V cp.async
// double-buffered; softmax in exp2 domain. smem rows: 72 halves (144B).
// ---------------------------------------------------------------------------
#define FSTW 36
#define QS_W (128 * FSTW)
#define KS_W (64 * FSTW)
#define VS_W (64 * FSTW)
#define FLASH_SMEM ((QS_W + 2 * KS_W + 2 * VS_W) * 4)   // 55296 B

__global__ __launch_bounds__(256, 2) void flash_tc()
{
    extern __shared__ uint32_t fsm[];
    uint32_t* Qs = fsm;                   // [128][72h] fp16 (prescaled)
    uint32_t* Ks = fsm + QS_W;            // 2 x [64][72h]
    uint32_t* Vs = fsm + QS_W + 2 * KS_W; // 2 x [64][72h], layout [j][dk]

    const int qb = (gridDim.x - 1) - blockIdx.x;
    const int bh = blockIdx.y;
    const uint32_t* Qg = g_Qh + (size_t)bh * Sdim * 32;
    const uint32_t* Kg = g_Kh + (size_t)bh * Sdim * 32;
    const uint32_t* Vg = g_Vh + (size_t)bh * Sdim * 32;

    const int tid = threadIdx.x;
    const int warp = tid >> 5;
    const int lane = tid & 31;
    const int g = lane >> 2;
    const int t = lane & 3;
    const int r0w = warp * 16;
    const int lrow = lane & 15;
    const int lcol = (lane >> 4) * 16;

    const int srow = tid >> 2;            // staging row 0..63
    const int sc8  = (tid & 3) * 8;       // staging word offset

    // Stage Q (all 128 rows) + K/V tile 0 into buffer 0
    {
        const int row = tid >> 1;
        const int cw = (tid & 1) * 16;
        uint32_t dq = sptr(&Qs[row * FSTW + cw]);
        const uint32_t* sq = Qg + (size_t)(qb * 128 + row) * 32 + cw;
#pragma unroll
        for (int i = 0; i < 4; i++) cpa16(dq + i * 16, sq + i * 4);

        uint32_t dk = sptr(&Ks[srow * FSTW + sc8]);
        const uint32_t* sk = Kg + (size_t)srow * 32 + sc8;
        cpa16(dk, sk); cpa16(dk + 16, sk + 4);

        uint32_t dv = sptr(&Vs[srow * FSTW + sc8]);
        const uint32_t* sv = Vg + (size_t)srow * 32 + sc8;
        cpa16(dv, sv); cpa16(dv + 16, sv + 4);
    }
    CP_COMMIT();
    CP_WAIT0();
    __syncthreads();

    float m_[2] = {-1e30f, -1e30f};
    float l_[2] = {0.f, 0.f};
    float o[8][4];
#pragma unroll
    for (int nf = 0; nf < 8; nf++)
#pragma unroll
        for (int i = 0; i < 4; i++) o[nf][i] = 0.f;

    const uint32_t qbase = sptr(Qs);
    const int jmax = 2 * qb + 1;
    for (int j = 0; j <= jmax; j++) {
        const int buf = j & 1;
        const uint32_t kbase = sptr(Ks + buf * KS_W);
        const uint32_t vbase = sptr(Vs + buf * VS_W);

        // Prefetch tile j+1 into the other buffer
        if (j < jmax) {
            const int bn = buf ^ 1;
            uint32_t dk = sptr(&Ks[bn * KS_W + srow * FSTW + sc8]);
            const uint32_t* sk = Kg + (size_t)((j + 1) * 64 + srow) * 32 + sc8;
            cpa16(dk, sk); cpa16(dk + 16, sk + 4);
            uint32_t dv = sptr(&Vs[bn * VS_W + srow * FSTW + sc8]);
            const uint32_t* sv = Vg + (size_t)((j + 1) * 64 + srow) * 32 + sc8;
            cpa16(dv, sv); cpa16(dv + 16, sv + 4);
            CP_COMMIT();
        }

        // ---- S = Q @ K^T (fp16 m16n8k16) ----
        float sacc[8][4];
#pragma unroll
        for (int nf = 0; nf < 8; nf++)
#pragma unroll
            for (int i = 0; i < 4; i++) sacc[nf][i] = 0.f;

#pragma unroll
        for (int ks = 0; ks < 4; ks++) {
            uint32_t a[4];
            ldmx4(a, qbase + (r0w + lrow) * 144 + ks * 32 + lcol);
#pragma unroll
            for (int np2 = 0; np2 < 4; np2++) {
                uint32_t b[4];
                ldmx4(b, kbase + (np2 * 16 + lrow) * 144 + ks * 32 + lcol);
                mma_f16(sacc[2 * np2],     a, b[0], b[2]);
                mma_f16(sacc[2 * np2 + 1], a, b[1], b[3]);
            }
        }

        // ---- causal mask on diagonal tiles ----
        if (j >= 2 * qb) {
            const int rg0 = qb * 128 + r0w + g;
            const int rg1 = rg0 + 8;
            const int cb = j * 64;
#pragma unroll
            for (int nf = 0; nf < 8; nf++) {
#pragma unroll
                for (int c = 0; c < 2; c++) {
                    int col = cb + nf * 8 + 2 * t + c;
                    if (col > rg0) sacc[nf][c] = -1e30f;
                    if (col > rg1) sacc[nf][2 + c] = -1e30f;
                }
            }
        }

        // ---- online softmax (exp2 domain) ----
#pragma unroll
        for (int r = 0; r < 2; r++) {
            const int off = r * 2;
            float tm = -1e30f;
#pragma unroll
            for (int nf = 0; nf < 8; nf++)
                tm = fmaxf(tm, fmaxf(sacc[nf][off], sacc[nf][off + 1]));
            tm = fmaxf(tm, __shfl_xor_sync(0xffffffffu, tm, 1));
            tm = fmaxf(tm, __shfl_xor_sync(0xffffffffu, tm, 2));
            float mnew = fmaxf(m_[r], tm);
            float fac = ex2(m_[r] - mnew);
            float rs = 0.f;
#pragma unroll
            for (int nf = 0; nf < 8; nf++) {
                float p0 = ex2(sacc[nf][off] - mnew);
                float p1 = ex2(sacc[nf][off + 1] - mnew);
                sacc[nf][off] = p0;
                sacc[nf][off + 1] = p1;
                rs += p0 + p1;
            }
            rs += __shfl_xor_sync(0xffffffffu, rs, 1);
            rs += __shfl_xor_sync(0xffffffffu, rs, 2);
            l_[r] = l_[r] * fac + rs;
            m_[r] = mnew;
#pragma unroll
            for (int nf = 0; nf < 8; nf++) {
                o[nf][off] *= fac;
                o[nf][off + 1] *= fac;
            }
        }

        // ---- pack P to fp16 A-frags (registers only) ----
        uint32_t ap[4][4];
#pragma unroll
        for (int kb = 0; kb < 4; kb++) {
            ap[kb][0] = pkh2(sacc[2 * kb][0], sacc[2 * kb][1]);
            ap[kb][1] = pkh2(sacc[2 * kb][2], sacc[2 * kb][3]);
            ap[kb][2] = pkh2(sacc[2 * kb + 1][0], sacc[2 * kb + 1][1]);
            ap[kb][3] = pkh2(sacc[2 * kb + 1][2], sacc[2 * kb + 1][3]);
        }

        // ---- O += P @ V (fp16, V B-frags via ldmatrix.trans) ----
#pragma unroll
        for (int np = 0; np < 4; np++) {
#pragma unroll
            for (int kb = 0; kb < 4; kb++) {
                uint32_t haddr = (uint32_t)((kb * 16 + lrow) * (2 * FSTW)
                                            + np * 16 + ((lane & 16) >> 1));
                uint32_t r0, r1, r2, r3;
                ldmx4t(r0, r1, r2, r3, vbase + haddr * 2);
                mma_f16(o[2 * np],     ap[kb], r0, r1);
                mma_f16(o[2 * np + 1], ap[kb], r2, r3);
            }
        }

        if (j < jmax) CP_WAIT0();
        __syncthreads();
    }

    // ---- epilogue: normalize, pack fp16 ctx ----
    const int b = bh / Hnum;
    const int h = bh % Hnum;
    const float inv0 = 1.f / l_[0];
    const float inv1 = 1.f / l_[1];
    const int row0 = qb * 128 + r0w + g;
#pragma unroll
    for (int nf = 0; nf < 8; nf++) {
        int cw = h * 32 + nf * 4 + t;
        g_ctx[(size_t)(b * Sdim + row0) * (Ddim / 2) + cw] =
            pkh2(o[nf][0] * inv0, o[nf][1] * inv0);
        g_ctx[(size_t)(b * Sdim + row0 + 8) * (Ddim / 2) + cw] =
            pkh2(o[nf][2] * inv1, o[nf][3] * inv1);
    }
}

// ---------------------------------------------------------------------------
// Launch
// ---------------------------------------------------------------------------
extern "C" void kernel_launch(void* const* d_in, const int* in_sizes, int n_in,
                              void* d_out, int out_size)
{
    const float* q  = (const float*)d_in[0];
    const float* k  = (const float*)d_in[1];
    const float* v  = (const float*)d_in[2];
    const float* Wq = (const float*)d_in[3];
    const float* Wk = (const float*)d_in[4];
    const float* Wv = (const float*)d_in[5];
    const float* Wo = (const float*)d_in[6];
    // d_in[7] = mask: known causal tril, handled analytically in flash_tc
    float* out = (float*)d_out;

    cudaFuncSetAttribute(proj_qkv, cudaFuncAttributeMaxDynamicSharedMemorySize, PROJ_SMEM);
    cudaFuncSetAttribute(proj_out, cudaFuncAttributeMaxDynamicSharedMemorySize, PROJ_SMEM);
    cudaFuncSetAttribute(flash_tc, cudaFuncAttributeMaxDynamicSharedMemorySize, FLASH_SMEM);

    preround_all<<<dim3(IN_BLOCKS, 7), 256>>>(q, k, v, Wq, Wk, Wv, Wo);

    proj_qkv<<<dim3(Ddim / 128, MROWS / 128, 3), 256, PROJ_SMEM>>>();

    flash_tc<<<dim3(Sdim / 128, BHnum), 256, FLASH_SMEM>>>();

    proj_out<<<dim3(Ddim / 128, MROWS / 128), 256, PROJ_SMEM>>>(out);
}

// round 17
// speedup vs baseline: 1.1414x; 1.0091x over previous
#include <cuda_runtime.h>
#include <stdint.h>

// Problem constants
#define Bdim 2
#define Sdim 4096
#define Ddim 768
#define Hnum 12
#define DKdim 64
#define BHnum (Bdim * Hnum)        // 24
#define MROWS (Bdim * Sdim)        // 8192
#define QSCALE (0.125f * 1.4426950408889634f)   // 1/sqrt(64) * log2(e)

// Scratch (device globals). All interchange data is fp16x2-packed (uint32).
__device__ uint32_t g_qr[(size_t)MROWS * Ddim / 2];
__device__ uint32_t g_kr[(size_t)MROWS * Ddim / 2];
__device__ uint32_t g_vr[(size_t)MROWS * Ddim / 2];
__device__ uint32_t g_wq[(size_t)Ddim * Ddim / 2];
__device__ uint32_t g_wk[(size_t)Ddim * Ddim / 2];
__device__ uint32_t g_wv[(size_t)Ddim * Ddim / 2];
__device__ uint32_t g_wo[(size_t)Ddim * Ddim / 2];
__device__ uint32_t g_Qh[(size_t)BHnum * Sdim * 32];   // [bh][s][dk/2], prescaled
__device__ uint32_t g_Kh[(size_t)BHnum * Sdim * 32];
__device__ uint32_t g_Vh[(size_t)BHnum * Sdim * 32];
__device__ uint32_t g_ctx[(size_t)MROWS * Ddim / 2];

// ---------------------------------------------------------------------------
// PTX helpers
// ---------------------------------------------------------------------------
__device__ __forceinline__ void mma_f16(float* c, const uint32_t* a, uint32_t b0, uint32_t b1) {
    asm("mma.sync.aligned.m16n8k16.row.col.f32.f16.f16.f32 "
        "{%0,%1,%2,%3},{%4,%5,%6,%7},{%8,%9},{%0,%1,%2,%3};"
        : "+f"(c[0]), "+f"(c[1]), "+f"(c[2]), "+f"(c[3])
        : "r"(a[0]), "r"(a[1]), "r"(a[2]), "r"(a[3]), "r"(b0), "r"(b1));
}
__device__ __forceinline__ uint32_t pkh2(float lo, float hi) {
    uint32_t r;
    asm("cvt.rn.f16x2.f32 %0, %1, %2;" : "=r"(r) : "f"(hi), "f"(lo));
    return r;
}
__device__ __forceinline__ float ex2(float x) {
    float r;
    asm("ex2.approx.ftz.f32 %0, %1;" : "=f"(r) : "f"(x));
    return r;
}
__device__ __forceinline__ uint32_t sptr(const void* p) {
    return (uint32_t)__cvta_generic_to_shared(p);
}
__device__ __forceinline__ void ldmx4(uint32_t* r, uint32_t addr) {
    asm volatile("ldmatrix.sync.aligned.m8n8.x4.shared.b16 {%0,%1,%2,%3}, [%4];"
                 : "=r"(r[0]), "=r"(r[1]), "=r"(r[2]), "=r"(r[3]) : "r"(addr));
}
__device__ __forceinline__ void ldmx4t(uint32_t& r0, uint32_t& r1, uint32_t& r2, uint32_t& r3,
                                       uint32_t addr) {
    asm volatile("ldmatrix.sync.aligned.m8n8.x4.trans.shared.b16 {%0,%1,%2,%3}, [%4];"
                 : "=r"(r0), "=r"(r1), "=r"(r2), "=r"(r3) : "r"(addr));
}
__device__ __forceinline__ void cpa16(uint32_t dst, const void* src) {
    asm volatile("cp.async.ca.shared.global [%0], [%1], 16;" :: "r"(dst), "l"(src));
}
#define CP_COMMIT() asm volatile("cp.async.commit_group;")
#define CP_WAIT0()  asm volatile("cp.async.wait_group 0;")
#define CP_WAIT1()  asm volatile("cp.async.wait_group 1;")
#define CP_WAIT2()  asm volatile("cp.async.wait_group 2;")

// ---------------------------------------------------------------------------
// Pre-round pass (merged, single launch): f32 -> fp16. y<3: q/k/v inputs;
// y>=3: weights (Wq pre-scaled by QSCALE). Short slices early-exit.
// ---------------------------------------------------------------------------
#define IN_BLOCKS ((MROWS * Ddim) / 2048)   // 3072
#define W_BLOCKS  ((Ddim * Ddim) / 2048)    // 288

__global__ __launch_bounds__(256) void preround_all(const float* __restrict__ q,
                                                    const float* __restrict__ k,
                                                    const float* __restrict__ v,
                                                    const float* __restrict__ Wq,
                                                    const float* __restrict__ Wk,
                                                    const float* __restrict__ Wv,
                                                    const float* __restrict__ Wo)
{
    const int y = blockIdx.y;
    if (y >= 3 && blockIdx.x >= W_BLOCKS) return;
    const size_t i = ((size_t)blockIdx.x * 256 + threadIdx.x) * 8;
    const float* s;
    uint32_t* d;
    float sc = 1.0f;
    switch (y) {
        case 0: s = q;  d = g_qr; break;
        case 1: s = k;  d = g_kr; break;
        case 2: s = v;  d = g_vr; break;
        case 3: s = Wq; d = g_wq; sc = QSCALE; break;
        case 4: s = Wk; d = g_wk; break;
        case 5: s = Wv; d = g_wv; break;
        default: s = Wo; d = g_wo; break;
    }
    float4 x0 = *(const float4*)(s + i);
    float4 x1 = *(const float4*)(s + i + 4);
    *(uint4*)(d + i / 2) = make_uint4(pkh2(x0.x * sc, x0.y * sc), pkh2(x0.z * sc, x0.w * sc),
                                      pkh2(x1.x * sc, x1.y * sc), pkh2(x1.z * sc, x1.w * sc));
}

// ---------------------------------------------------------------------------
// Projection GEMM (fp16 m16n8k16, 4-stage cp.async pipeline, BK=32):
// C = A @ W^T. BM=BN=128; 8 warps (2m x 4n), warp tile 64x32.
// smem rows 40 halves (80B) -> conflict-free ldmatrix (R8-proven layout).
// Loads issued 3 chunks ahead; wait_group keeps chunk c ready at compute.
// ---------------------------------------------------------------------------
#define PSTW 20                      // row stride in words (40 halves = 80B)
#define PBUF (128 * PSTW)            // 2560 words per operand tile (10KB)
#define STAGEW (2 * PBUF)            // 5120 words per stage (A+B, 20KB)
#define NKC (Ddim / 32)              // 24 chunks
#define NSTG 4
#define PROJ_SMEM (NSTG * STAGEW * 4)   // 81920 B

__device__ __forceinline__ void proj_stage(const uint32_t* __restrict__ Ap,
                                           const uint32_t* __restrict__ W,
                                           uint32_t* psm, int kc, int m0, int n0)
{
    const int tid = threadIdx.x;
    const int r = tid & 127;
    uint32_t* base = psm + (kc & (NSTG - 1)) * STAGEW;
    // one 64B half-row (16 words) per thread: tid<128 stage A, >=128 stage B
    const uint32_t* src = (tid < 128)
        ? Ap + (size_t)(m0 + r) * (Ddim / 2) + kc * 16
        : W  + (size_t)(n0 + r) * (Ddim / 2) + kc * 16;
    uint32_t dst = sptr(base + ((tid < 128) ? 0 : PBUF) + r * PSTW);
#pragma unroll
    for (int i = 0; i < 4; i++) cpa16(dst + i * 16, src + i * 4);
}

__device__ __forceinline__ void proj_body(const uint32_t* __restrict__ Ap,
                                          const uint32_t* __restrict__ W,
                                          float* __restrict__ Cp, int mode,
                                          int m0, int n0, uint32_t* psm)
{
    const int tid = threadIdx.x;
    const int warp = tid >> 5;
    const int lane = tid & 31;
    const int g = lane >> 2;
    const int t = lane & 3;
    const int m0w = (warp >> 2) * 64;
    const int n0w = (warp & 3) * 32;
    const int lrow = lane & 15;
    const int lcol = (lane >> 4) * 16;

    float acc[4][4][4];
#pragma unroll
    for (int mf = 0; mf < 4; mf++)
#pragma unroll
        for (int nf = 0; nf < 4; nf++)
#pragma unroll
            for (int i = 0; i < 4; i++) acc[mf][nf][i] = 0.f;

    // Prologue: stage chunks 0..2 (3 groups in flight)
    proj_stage(Ap, W, psm, 0, m0, n0);
    CP_COMMIT();
    proj_stage(Ap, W, psm, 1, m0, n0);
    CP_COMMIT();
    proj_stage(Ap, W, psm, 2, m0, n0);
    CP_COMMIT();
    CP_WAIT2();          // chunk 0 complete
    __syncthreads();

    // Hoisted per-lane fragment bases (stage 0); stage s = +s*20480 bytes
    const uint32_t abase0 = sptr(psm) + (m0w + lrow) * 80 + lcol;
    const uint32_t bbase0 = sptr(psm) + PBUF * 4 + (n0w + lrow) * 80 + lcol;

    for (int kc = 0; kc < NKC; kc++) {
        const uint32_t soff = (uint32_t)(kc & (NSTG - 1)) * (STAGEW * 4);
#pragma unroll
        for (int ks = 0; ks < 2; ks++) {
            uint32_t a[4][4];
#pragma unroll
            for (int mf = 0; mf < 4; mf++)
                ldmx4(a[mf], abase0 + soff + mf * 1280 + ks * 32);
#pragma unroll
            for (int np2 = 0; np2 < 2; np2++) {
                uint32_t b[4];
                ldmx4(b, bbase0 + soff + np2 * 1280 + ks * 32);
#pragma unroll
                for (int mf = 0; mf < 4; mf++) {
                    mma_f16(acc[mf][2 * np2],     a[mf], b[0], b[2]);
                    mma_f16(acc[mf][2 * np2 + 1], a[mf], b[1], b[3]);
                }
            }
        }
        // Stage chunk kc+3 (reuses buffer of chunk kc-1; all warps are past
        // it: end-of-previous-iteration sync came after its compute).
        if (kc + 3 < NKC) {
            proj_stage(Ap, W, psm, kc + 3, m0, n0);
            CP_COMMIT();
        }
        // Ensure chunk kc+1 is complete before the next compute.
        if (kc + 3 < NKC)      { CP_WAIT2(); }
        else if (kc + 2 < NKC) { CP_WAIT1(); }
        else if (kc + 1 < NKC) { CP_WAIT0(); }
        __syncthreads();
    }

    // Epilogue
#pragma unroll
    for (int mf = 0; mf < 4; mf++) {
#pragma unroll
        for (int nf = 0; nf < 4; nf++) {
            int row = m0 + m0w + mf * 16 + g;
            int col = n0 + n0w + nf * 8 + 2 * t;
            if (mode == 3) {
                *(float2*)(Cp + (size_t)row * Ddim + col) =
                    make_float2(acc[mf][nf][0], acc[mf][nf][1]);
                *(float2*)(Cp + (size_t)(row + 8) * Ddim + col) =
                    make_float2(acc[mf][nf][2], acc[mf][nf][3]);
            } else {
                int h = col >> 6, dk = col & 63;
                int b = row >> 12;
                int s = row & 4095;
                size_t r0 = (size_t)(b * Hnum + h) * Sdim + s;
                size_t r1 = r0 + 8;
                uint32_t* base = (mode == 0) ? g_Qh : (mode == 1) ? g_Kh : g_Vh;
                base[r0 * 32 + (dk >> 1)] = pkh2(acc[mf][nf][0], acc[mf][nf][1]);
                base[r1 * 32 + (dk >> 1)] = pkh2(acc[mf][nf][2], acc[mf][nf][3]);
            }
        }
    }
}

__global__ __launch_bounds__(256, 2) void proj_qkv()
{
    extern __shared__ uint32_t psm[];
    const int z = blockIdx.z;
    const uint32_t* A = (z == 0) ? g_qr : (z == 1) ? g_kr : g_vr;
    const uint32_t* W = (z == 0) ? g_wq : (z == 1) ? g_wk : g_wv;
    proj_body(A, W, nullptr, z, blockIdx.y * 128, blockIdx.x * 128, psm);
}

__global__ __launch_bounds__(256, 2) void proj_out(float* __restrict__ Cp)
{
    extern __shared__ uint32_t psm[];
    proj_body(g_ctx, g_wo, Cp, 3, blockIdx.y * 128, blockIdx.x * 128, psm);
}

// ---------------------------------------------------------------------------
// Flash attention (R8 version, verbatim): all-fp16 operands. BQ=128, BK=64.
// QK^T and PV both fp16 m16n8k16; frags via ldmatrix; K/V cp.async
// double-buffered; softmax in exp2 domain. smem rows: 72 halves (144B).
// ---------------------------------------------------------------------------
#define FSTW 36
#define QS_W (128 * FSTW)
#define KS_W (64 * FSTW)
#define VS_W (64 * FSTW)
#define FLASH_SMEM ((QS_W + 2 * KS_W + 2 * VS_W) * 4)   // 55296 B

__global__ __launch_bounds__(256, 2) void flash_tc()
{
    extern __shared__ uint32_t fsm[];
    uint32_t* Qs = fsm;                   // [128][72h] fp16 (prescaled)
    uint32_t* Ks = fsm + QS_W;            // 2 x [64][72h]
    uint32_t* Vs = fsm + QS_W + 2 * KS_W; // 2 x [64][72h], layout [j][dk]

    const int qb = (gridDim.x - 1) - blockIdx.x;
    const int bh = blockIdx.y;
    const uint32_t* Qg = g_Qh + (size_t)bh * Sdim * 32;
    const uint32_t* Kg = g_Kh + (size_t)bh * Sdim * 32;
    const uint32_t* Vg = g_Vh + (size_t)bh * Sdim * 32;

    const int tid = threadIdx.x;
    const int warp = tid >> 5;
    const int lane = tid & 31;
    const int g = lane >> 2;
    const int t = lane & 3;
    const int r0w = warp * 16;
    const int lrow = lane & 15;
    const int lcol = (lane >> 4) * 16;

    const int srow = tid >> 2;            // staging row 0..63
    const int sc8  = (tid & 3) * 8;       // staging word offset

    // Stage Q (all 128 rows) + K/V tile 0 into buffer 0
    {
        const int row = tid >> 1;
        const int cw = (tid & 1) * 16;
        uint32_t dq = sptr(&Qs[row * FSTW + cw]);
        const uint32_t* sq = Qg + (size_t)(qb * 128 + row) * 32 + cw;
#pragma unroll
        for (int i = 0; i < 4; i++) cpa16(dq + i * 16, sq + i * 4);

        uint32_t dk = sptr(&Ks[srow * FSTW + sc8]);
        const uint32_t* sk = Kg + (size_t)srow * 32 + sc8;
        cpa16(dk, sk); cpa16(dk + 16, sk + 4);

        uint32_t dv = sptr(&Vs[srow * FSTW + sc8]);
        const uint32_t* sv = Vg + (size_t)srow * 32 + sc8;
        cpa16(dv, sv); cpa16(dv + 16, sv + 4);
    }
    CP_COMMIT();
    CP_WAIT0();
    __syncthreads();

    float m_[2] = {-1e30f, -1e30f};
    float l_[2] = {0.f, 0.f};
    float o[8][4];
#pragma unroll
    for (int nf = 0; nf < 8; nf++)
#pragma unroll
        for (int i = 0; i < 4; i++) o[nf][i] = 0.f;

    const uint32_t qbase = sptr(Qs);
    const int jmax = 2 * qb + 1;
    for (int j = 0; j <= jmax; j++) {
        const int buf = j & 1;
        const uint32_t kbase = sptr(Ks + buf * KS_W);
        const uint32_t vbase = sptr(Vs + buf * VS_W);

        // Prefetch tile j+1 into the other buffer
        if (j < jmax) {
            const int bn = buf ^ 1;
            uint32_t dk = sptr(&Ks[bn * KS_W + srow * FSTW + sc8]);
            const uint32_t* sk = Kg + (size_t)((j + 1) * 64 + srow) * 32 + sc8;
            cpa16(dk, sk); cpa16(dk + 16, sk + 4);
            uint32_t dv = sptr(&Vs[bn * VS_W + srow * FSTW + sc8]);
            const uint32_t* sv = Vg + (size_t)((j + 1) * 64 + srow) * 32 + sc8;
            cpa16(dv, sv); cpa16(dv + 16, sv + 4);
            CP_COMMIT();
        }

        // ---- S = Q @ K^T (fp16 m16n8k16) ----
        float sacc[8][4];
#pragma unroll
        for (int nf = 0; nf < 8; nf++)
#pragma unroll
            for (int i = 0; i < 4; i++) sacc[nf][i] = 0.f;

#pragma unroll
        for (int ks = 0; ks < 4; ks++) {
            uint32_t a[4];
            ldmx4(a, qbase + (r0w + lrow) * 144 + ks * 32 + lcol);
#pragma unroll
            for (int np2 = 0; np2 < 4; np2++) {
                uint32_t b[4];
                ldmx4(b, kbase + (np2 * 16 + lrow) * 144 + ks * 32 + lcol);
                mma_f16(sacc[2 * np2],     a, b[0], b[2]);
                mma_f16(sacc[2 * np2 + 1], a, b[1], b[3]);
            }
        }

        // ---- causal mask on diagonal tiles ----
        if (j >= 2 * qb) {
            const int rg0 = qb * 128 + r0w + g;
            const int rg1 = rg0 + 8;
            const int cb = j * 64;
#pragma unroll
            for (int nf = 0; nf < 8; nf++) {
#pragma unroll
                for (int c = 0; c < 2; c++) {
                    int col = cb + nf * 8 + 2 * t + c;
                    if (col > rg0) sacc[nf][c] = -1e30f;
                    if (col > rg1) sacc[nf][2 + c] = -1e30f;
                }
            }
        }

        // ---- online softmax (exp2 domain) ----
#pragma unroll
        for (int r = 0; r < 2; r++) {
            const int off = r * 2;
            float tm = -1e30f;
#pragma unroll
            for (int nf = 0; nf < 8; nf++)
                tm = fmaxf(tm, fmaxf(sacc[nf][off], sacc[nf][off + 1]));
            tm = fmaxf(tm, __shfl_xor_sync(0xffffffffu, tm, 1));
            tm = fmaxf(tm, __shfl_xor_sync(0xffffffffu, tm, 2));
            float mnew = fmaxf(m_[r], tm);
            float fac = ex2(m_[r] - mnew);
            float rs = 0.f;
#pragma unroll
            for (int nf = 0; nf < 8; nf++) {
                float p0 = ex2(sacc[nf][off] - mnew);
                float p1 = ex2(sacc[nf][off + 1] - mnew);
                sacc[nf][off] = p0;
                sacc[nf][off + 1] = p1;
                rs += p0 + p1;
            }
            rs += __shfl_xor_sync(0xffffffffu, rs, 1);
            rs += __shfl_xor_sync(0xffffffffu, rs, 2);
            l_[r] = l_[r] * fac + rs;
            m_[r] = mnew;
#pragma unroll
            for (int nf = 0; nf < 8; nf++) {
                o[nf][off] *= fac;
                o[nf][off + 1] *= fac;
            }
        }

        // ---- pack P to fp16 A-frags (registers only) ----
        uint32_t ap[4][4];
#pragma unroll
        for (int kb = 0; kb < 4; kb++) {
            ap[kb][0] = pkh2(sacc[2 * kb][0], sacc[2 * kb][1]);
            ap[kb][1] = pkh2(sacc[2 * kb][2], sacc[2 * kb][3]);
            ap[kb][2] = pkh2(sacc[2 * kb + 1][0], sacc[2 * kb + 1][1]);
            ap[kb][3] = pkh2(sacc[2 * kb + 1][2], sacc[2 * kb + 1][3]);
        }

        // ---- O += P @ V (fp16, V B-frags via ldmatrix.trans) ----
#pragma unroll
        for (int np = 0; np < 4; np++) {
#pragma unroll
            for (int kb = 0; kb < 4; kb++) {
                uint32_t haddr = (uint32_t)((kb * 16 + lrow) * (2 * FSTW)
                                            + np * 16 + ((lane & 16) >> 1));
                uint32_t r0, r1, r2, r3;
                ldmx4t(r0, r1, r2, r3, vbase + haddr * 2);
                mma_f16(o[2 * np],     ap[kb], r0, r1);
                mma_f16(o[2 * np + 1], ap[kb], r2, r3);
            }
        }

        if (j < jmax) CP_WAIT0();
        __syncthreads();
    }

    // ---- epilogue: normalize, pack fp16 ctx ----
    const int b = bh / Hnum;
    const int h = bh % Hnum;
    const float inv0 = 1.f / l_[0];
    const float inv1 = 1.f / l_[1];
    const int row0 = qb * 128 + r0w + g;
#pragma unroll
    for (int nf = 0; nf < 8; nf++) {
        int cw = h * 32 + nf * 4 + t;
        g_ctx[(size_t)(b * Sdim + row0) * (Ddim / 2) + cw] =
            pkh2(o[nf][0] * inv0, o[nf][1] * inv0);
        g_ctx[(size_t)(b * Sdim + row0 + 8) * (Ddim / 2) + cw] =
            pkh2(o[nf][2] * inv1, o[nf][3] * inv1);
    }
}

// ---------------------------------------------------------------------------
// Launch
// ---------------------------------------------------------------------------
extern "C" void kernel_launch(void* const* d_in, const int* in_sizes, int n_in,
                              void* d_out, int out_size)
{
    const float* q  = (const float*)d_in[0];
    const float* k  = (const float*)d_in[1];
    const float* v  = (const float*)d_in[2];
    const float* Wq = (const float*)d_in[3];
    const float* Wk = (const float*)d_in[4];
    const float* Wv = (const float*)d_in[5];
    const float* Wo = (const float*)d_in[6];
    // d_in[7] = mask: known causal tril, handled analytically in flash_tc
    float* out = (float*)d_out;

    cudaFuncSetAttribute(proj_qkv, cudaFuncAttributeMaxDynamicSharedMemorySize, PROJ_SMEM);
    cudaFuncSetAttribute(proj_out, cudaFuncAttributeMaxDynamicSharedMemorySize, PROJ_SMEM);
    cudaFuncSetAttribute(flash_tc, cudaFuncAttributeMaxDynamicSharedMemorySize, FLASH_SMEM);

    preround_all<<<dim3(IN_BLOCKS, 7), 256>>>(q, k, v, Wq, Wk, Wv, Wo);

    proj_qkv<<<dim3(Ddim / 128, MROWS / 128, 3), 256, PROJ_SMEM>>>();

    flash_tc<<<dim3(Sdim / 128, BHnum), 256, FLASH_SMEM>>>();

    proj_out<<<dim3(Ddim / 128, MROWS / 128), 256, PROJ_SMEM>>>(out);
}